// round 1
// baseline (speedup 1.0000x reference)
#include <cuda_runtime.h>
#include <math.h>

#define B_    2
#define L_    2048
#define DIM_  1024
#define H_    16
#define DH_   64
#define N3_   3072
#define SCALE_ 0.125f        // 64^-0.5
#define EPS_  1e-10f

// Scratch (device globals: allocation is forbidden)
__device__ float g_qkv[B_ * L_ * N3_];   // [b, l, 3*1024] : q at +0, k at +1024, v at +2048
__device__ float g_z[B_ * L_ * DIM_];    // [b, l, h*dh]

// ---------------------------------------------------------------------------
// Generic fp32 SGEMM: C[M,N] = A[M,K] @ B[K,N] (+ bias). 128x128x8 tiles,
// 256 threads, 8x8 per thread. All dims divide evenly for our shapes.
// ---------------------------------------------------------------------------
template <bool BIAS>
__global__ __launch_bounds__(256) void sgemm128(
    const float* __restrict__ A, const float* __restrict__ Bm,
    const float* __restrict__ bias, float* __restrict__ C,
    int M, int N, int K)
{
    const int BM = 128, BN = 128, BK = 8;
    __shared__ float As[BK][BM];   // transposed A tile
    __shared__ float Bs[BK][BN];

    int tid = threadIdx.x;
    int bx = blockIdx.x, by = blockIdx.y;

    int aRow = tid >> 1;          // 0..127
    int aCol = (tid & 1) * 4;     // 0 or 4
    int bRow = tid >> 5;          // 0..7
    int bCol = (tid & 31) * 4;    // 0..124

    int tr = (tid >> 4) * 8;      // thread row base in tile
    int tc = (tid & 15) * 8;      // thread col base in tile

    const float* Ag = A + (size_t)(by * BM) * K;
    const float* Bg = Bm + bx * BN;

    float acc[8][8];
    #pragma unroll
    for (int i = 0; i < 8; i++)
        #pragma unroll
        for (int j = 0; j < 8; j++) acc[i][j] = 0.0f;

    for (int k0 = 0; k0 < K; k0 += BK) {
        float4 av = *(const float4*)(Ag + (size_t)aRow * K + k0 + aCol);
        As[aCol + 0][aRow] = av.x;
        As[aCol + 1][aRow] = av.y;
        As[aCol + 2][aRow] = av.z;
        As[aCol + 3][aRow] = av.w;
        float4 bv = *(const float4*)(Bg + (size_t)(k0 + bRow) * N + bCol);
        *(float4*)&Bs[bRow][bCol] = bv;
        __syncthreads();

        #pragma unroll
        for (int k = 0; k < BK; k++) {
            float ar[8], br[8];
            *(float4*)&ar[0] = *(const float4*)&As[k][tr];
            *(float4*)&ar[4] = *(const float4*)&As[k][tr + 4];
            *(float4*)&br[0] = *(const float4*)&Bs[k][tc];
            *(float4*)&br[4] = *(const float4*)&Bs[k][tc + 4];
            #pragma unroll
            for (int i = 0; i < 8; i++)
                #pragma unroll
                for (int j = 0; j < 8; j++)
                    acc[i][j] += ar[i] * br[j];
        }
        __syncthreads();
    }

    #pragma unroll
    for (int i = 0; i < 8; i++) {
        size_t row = (size_t)(by * BM + tr + i);
        #pragma unroll
        for (int j = 0; j < 8; j += 4) {
            int col = bx * BN + tc + j;
            float4 v;
            v.x = acc[i][j + 0]; v.y = acc[i][j + 1];
            v.z = acc[i][j + 2]; v.w = acc[i][j + 3];
            if (BIAS) {
                float4 bb = *(const float4*)&bias[col];
                v.x += bb.x; v.y += bb.y; v.z += bb.z; v.w += bb.w;
            }
            *(float4*)&C[row * N + col] = v;
        }
    }
}

// ---------------------------------------------------------------------------
// Flash-style attention with post-softmax multiplicative mask + renorm.
// Online softmax tracks TWO running sums per query row:
//   Zf = sum e^{s-m}            (full softmax denominator)
//   Lm = sum e^{s-m} * mask     (masked numerator sum)
// Final: z = acc / (Lm + EPS*Zf)   == softmax->mask->renorm exactly.
// Grid: (l/64, heads, batch). Block: 256 threads. 64-row Q tile, 64-wide
// KV blocks. 4x4 microtile per thread for both S=QK^T and O+=PV.
// ---------------------------------------------------------------------------
__global__ __launch_bounds__(256) void attn_kernel(
    const float* __restrict__ qkv, const float* __restrict__ mask,
    float* __restrict__ z)
{
    const int ST = 68;   // 64 + 4 pad (keeps float4 16B-aligned rows)
    extern __shared__ float sm[];
    float* QT  = sm;                // [d][r]   d*ST + r
    float* KT  = QT  + 64 * ST;     // [d][c]
    float* Vs  = KT  + 64 * ST;     // [j][c]
    float* Ssh = Vs  + 64 * ST;     // [r][j]
    float* PT  = Ssh + 64 * ST;     // [j][r]
    float* MSK = PT  + 64 * ST;     // [r][j]
    __shared__ float m_s[64], Zf[64], Lm[64], corr[64];

    int tid  = threadIdx.x;
    int lane = tid & 31, warp = tid >> 5;
    int b = blockIdx.z, h = blockIdx.y;
    int q0 = blockIdx.x * 64;

    const float* qbase = qkv + (size_t)b * L_ * N3_ + h * DH_;
    const float* kbase = qbase + 1024;
    const float* vbase = qbase + 2048;

    // Load Q tile transposed: QT[d][r]
    for (int idx = tid; idx < 64 * 64; idx += 256) {
        int r = idx >> 6, d = idx & 63;
        QT[d * ST + r] = qbase[(size_t)(q0 + r) * N3_ + d];
    }
    if (tid < 64) { m_s[tid] = -INFINITY; Zf[tid] = 0.0f; Lm[tid] = 0.0f; }

    int tr4 = (tid >> 4) * 4;   // 4-row group
    int tc4 = (tid & 15) * 4;   // 4-col group
    float oacc[4][4] = {};

    __syncthreads();

    for (int k0 = 0; k0 < L_; k0 += 64) {
        // ---- load K^T, V, mask block ----
        for (int idx = tid; idx < 64 * 64; idx += 256) {
            int c = idx >> 6, d = idx & 63;
            KT[d * ST + c] = kbase[(size_t)(k0 + c) * N3_ + d];
        }
        for (int idx = tid; idx < 64 * 64; idx += 256) {
            int j = idx >> 6, c = idx & 63;
            Vs[j * ST + c] = vbase[(size_t)(k0 + j) * N3_ + c];
        }
        for (int idx = tid; idx < 64 * 64; idx += 256) {
            int r = idx >> 6, jj = idx & 63;
            MSK[r * ST + jj] = mask[((size_t)b * L_ + q0 + r) * L_ + k0 + jj];
        }
        __syncthreads();

        // ---- S = Q @ K^T * SCALE ----
        {
            float sacc[4][4] = {};
            #pragma unroll 8
            for (int kk = 0; kk < 64; kk++) {
                float4 qv = *(const float4*)&QT[kk * ST + tr4];
                float4 kv = *(const float4*)&KT[kk * ST + tc4];
                float qa[4] = {qv.x, qv.y, qv.z, qv.w};
                float ka[4] = {kv.x, kv.y, kv.z, kv.w};
                #pragma unroll
                for (int i = 0; i < 4; i++)
                    #pragma unroll
                    for (int j = 0; j < 4; j++)
                        sacc[i][j] += qa[i] * ka[j];
            }
            #pragma unroll
            for (int i = 0; i < 4; i++)
                #pragma unroll
                for (int j = 0; j < 4; j++)
                    Ssh[(tr4 + i) * ST + tc4 + j] = sacc[i][j] * SCALE_;
        }
        __syncthreads();

        // ---- online softmax row pass (warp w owns rows w*8..w*8+7) ----
        #pragma unroll
        for (int i = 0; i < 8; i++) {
            int r = warp * 8 + i;
            float s0 = Ssh[r * ST + lane];
            float s1 = Ssh[r * ST + 32 + lane];
            float mx = fmaxf(s0, s1);
            #pragma unroll
            for (int o = 16; o > 0; o >>= 1)
                mx = fmaxf(mx, __shfl_xor_sync(0xffffffffu, mx, o));
            float mprev = m_s[r];
            float mnew  = fmaxf(mprev, mx);
            float c  = __expf(mprev - mnew);          // exp(-inf)=0 first block
            float p0 = __expf(s0 - mnew);
            float p1 = __expf(s1 - mnew);
            float zs = p0 + p1;
            float pm0 = p0 * MSK[r * ST + lane];
            float pm1 = p1 * MSK[r * ST + 32 + lane];
            float ls = pm0 + pm1;
            #pragma unroll
            for (int o = 16; o > 0; o >>= 1) {
                zs += __shfl_xor_sync(0xffffffffu, zs, o);
                ls += __shfl_xor_sync(0xffffffffu, ls, o);
            }
            PT[lane * ST + r]        = pm0;
            PT[(lane + 32) * ST + r] = pm1;
            if (lane == 0) {
                m_s[r] = mnew;
                Zf[r]  = Zf[r] * c + zs;
                Lm[r]  = Lm[r] * c + ls;
                corr[r] = c;
            }
        }
        __syncthreads();

        // ---- rescale accumulator, O += P @ V ----
        {
            float c0 = corr[tr4 + 0], c1 = corr[tr4 + 1];
            float c2 = corr[tr4 + 2], c3 = corr[tr4 + 3];
            #pragma unroll
            for (int j = 0; j < 4; j++) {
                oacc[0][j] *= c0; oacc[1][j] *= c1;
                oacc[2][j] *= c2; oacc[3][j] *= c3;
            }
            #pragma unroll 8
            for (int kk = 0; kk < 64; kk++) {
                float4 pv = *(const float4*)&PT[kk * ST + tr4];
                float4 vv = *(const float4*)&Vs[kk * ST + tc4];
                float pa[4] = {pv.x, pv.y, pv.z, pv.w};
                float va[4] = {vv.x, vv.y, vv.z, vv.w};
                #pragma unroll
                for (int i = 0; i < 4; i++)
                    #pragma unroll
                    for (int j = 0; j < 4; j++)
                        oacc[i][j] += pa[i] * va[j];
            }
        }
        __syncthreads();
    }

    // ---- finalize: z = acc / (Lm + EPS*Zf), layout [b, l, h*dh] ----
    #pragma unroll
    for (int i = 0; i < 4; i++) {
        int r = tr4 + i;
        float inv = 1.0f / (Lm[r] + EPS_ * Zf[r]);
        #pragma unroll
        for (int j = 0; j < 4; j++)
            z[((size_t)b * L_ + q0 + r) * DIM_ + h * DH_ + tc4 + j] = oacc[i][j] * inv;
    }
}

// ---------------------------------------------------------------------------
extern "C" void kernel_launch(void* const* d_in, const int* in_sizes, int n_in,
                              void* d_out, int out_size)
{
    const float* x    = (const float*)d_in[0];   // [2,2048,1024]
    const float* mask = (const float*)d_in[1];   // [2,2048,2048]
    const float* Wqkv = (const float*)d_in[2];   // [1024,3072]
    const float* Wout = (const float*)d_in[3];   // [1024,1024]
    const float* bout = (const float*)d_in[4];   // [1024]
    float* out = (float*)d_out;                  // [2,2048,1024]

    float* qkvp = nullptr;
    float* zp   = nullptr;
    cudaGetSymbolAddress((void**)&qkvp, g_qkv);
    cudaGetSymbolAddress((void**)&zp,   g_z);

    const int ATTN_SMEM = 6 * 64 * 68 * (int)sizeof(float);  // 104448 B
    cudaFuncSetAttribute(attn_kernel,
                         cudaFuncAttributeMaxDynamicSharedMemorySize, ATTN_SMEM);

    // 1) QKV projection: [4096,1024] @ [1024,3072]
    sgemm128<false><<<dim3(N3_ / 128, (B_ * L_) / 128), 256>>>(
        x, Wqkv, nullptr, qkvp, B_ * L_, N3_, DIM_);

    // 2) attention (h fastest-varying after qtile -> mask L2 reuse across heads)
    attn_kernel<<<dim3(L_ / 64, H_, B_), 256, ATTN_SMEM>>>(qkvp, mask, zp);

    // 3) output projection + bias: [4096,1024] @ [1024,1024]
    sgemm128<true><<<dim3(DIM_ / 128, (B_ * L_) / 128), 256>>>(
        zp, Wout, bout, out, B_ * L_, DIM_, DIM_);
}